// round 4
// baseline (speedup 1.0000x reference)
#include <cuda_runtime.h>
#include <cuda_fp16.h>

#define NHEAD 4
#define ATT   16
#define COLD  64
#define AISD  64
#define MDIM  256
#define SKPAD 208
#define BMAX  8192

__device__ float g_W[(size_t)BMAX * MDIM];   // 8 MB scratch

typedef unsigned long long ull;

// ---- packed fp32x2 helpers ----
__device__ __forceinline__ ull fma2(ull a, ull b, ull c) {
    ull d;
    asm("fma.rn.f32x2 %0, %1, %2, %3;" : "=l"(d) : "l"(a), "l"(b), "l"(c));
    return d;
}
__device__ __forceinline__ ull add2(ull a, ull b) {
    ull d;
    asm("add.rn.f32x2 %0, %1, %2;" : "=l"(d) : "l"(a), "l"(b));
    return d;
}
__device__ __forceinline__ ull pack2(float x, float y) {
    ull r;
    asm("mov.b64 %0, {%1, %2};" : "=l"(r) : "f"(x), "f"(y));
    return r;
}
__device__ __forceinline__ float2 unpack2(ull a) {
    float2 f;
    asm("mov.b64 {%0, %1}, %2;" : "=f"(f.x), "=f"(f.y) : "l"(a));
    return f;
}
__device__ __forceinline__ ull h2f2(unsigned h) {
    ull r;
    asm("{\n\t.reg .b16 lo, hi;\n\t.reg .f32 flo, fhi;\n\t"
        "mov.b32 {lo, hi}, %1;\n\t"
        "cvt.f32.f16 flo, lo;\n\tcvt.f32.f16 fhi, hi;\n\t"
        "mov.b64 %0, {flo, fhi};\n\t}" : "=l"(r) : "r"(h));
    return r;
}

// ---------------------------------------------------------------------------
// K1 v4: W[b][h*64+a] = (1/8) sum_j (q[b]@Q)[h*16+j] * K[a][h*16+j]
// 16 batches/CTA. K staged in PADDED smem (kills 32-wf strided loads).
// ---------------------------------------------------------------------------
__global__ __launch_bounds__(256) void k1_w(const float* __restrict__ query,
                                            const float* __restrict__ Q,
                                            const float* __restrict__ Kw, int B) {
    __shared__ float sK[64 * 68];     // sK[a*68 + j], padded
    __shared__ float qT[64 * 20];     // qT[i*20 + b], padded (float4-aligned)
    __shared__ float qp[16 * 64];     // qp[b*64 + c]
    int b0 = blockIdx.x * 16, t = threadIdx.x;

    // q transposed into smem (4 passes of 4 batches)
#pragma unroll
    for (int p = 0; p < 4; p++) {
        int bb = p * 4 + (t >> 6), i = t & 63;
        float v = (b0 + bb < B) ? query[(size_t)(b0 + bb) * 64 + i] : 0.f;
        qT[i * 20 + bb] = v;
    }
    // stage K coalesced
    for (int idx = t; idx < 4096; idx += 256)
        sK[(idx >> 6) * 68 + (idx & 63)] = Kw[idx];
    __syncthreads();

    // qp: thread (bq = t>>6 handles 4 batches, c = t&63)
    {
        int bq = t >> 6, c = t & 63;
        float a0 = 0.f, a1 = 0.f, a2 = 0.f, a3 = 0.f;
#pragma unroll 8
        for (int i = 0; i < 64; i++) {
            float qv = Q[i * 64 + c];
            float4 qb = *(const float4*)(qT + i * 20 + bq * 4);
            a0 += qb.x * qv; a1 += qb.y * qv; a2 += qb.z * qv; a3 += qb.w * qv;
        }
        qp[(bq * 4 + 0) * 64 + c] = a0;
        qp[(bq * 4 + 1) * 64 + c] = a1;
        qp[(bq * 4 + 2) * 64 + c] = a2;
        qp[(bq * 4 + 3) * 64 + c] = a3;
    }
    __syncthreads();

    // W: t = h*64 + a ; K row held in regs, 16-batch loop with broadcast qp
    {
        int h = t >> 6, a = t & 63;
        const float4* K4 = (const float4*)(sK + a * 68 + h * 16);
        float4 k0 = K4[0], k1 = K4[1], k2 = K4[2], k3 = K4[3];
#pragma unroll
        for (int bb = 0; bb < 16; bb++) {
            const float4* q4 = (const float4*)(qp + bb * 64 + h * 16);
            float4 qa = q4[0], qb = q4[1], qc = q4[2], qd = q4[3];
            float wv = qa.x * k0.x + qa.y * k0.y + qa.z * k0.z + qa.w * k0.w
                     + qb.x * k1.x + qb.y * k1.y + qb.z * k1.z + qb.w * k1.w
                     + qc.x * k2.x + qc.y * k2.y + qc.z * k2.z + qc.w * k2.w
                     + qd.x * k3.x + qd.y * k3.y + qd.z * k3.z + qd.w * k3.w;
            if (b0 + bb < B)
                g_W[(size_t)(b0 + bb) * MDIM + t] = 0.125f * wv;
        }
    }
}

// ---------------------------------------------------------------------------
// K2: fused attention + output projection, one CTA per batch element.
// ---------------------------------------------------------------------------
#define SA_BYTES   (SKPAD * 64 * 2)          // 26624 fp16 swizzled tile
#define SW_OFF     SA_BYTES                  // 1024: W row / later ctx
#define SC_OFF     (SW_OFF + 1024)           // 3328: packed scores ull[2][SKPAD]
#define SINV_OFF   (SC_OFF + 3328)           // 32
#define PART_OFF   (SINV_OFF + 32)           // 4096: partials 4 x 256 floats
#define SMEM_BYTES (PART_OFF + 4096)

extern __shared__ char s_raw[];

__global__ __launch_bounds__(256, 4) void k2_fused(const float* __restrict__ act,
                                                   const float* __restrict__ V,
                                                   float* __restrict__ out, int nsk) {
    char*  sab  = s_raw;
    float* sw   = (float*)(s_raw + SW_OFF);
    ull*   scu  = (ull*)(s_raw + SC_OFF);
    float* sinv = (float*)(s_raw + SINV_OFF);
    float* partf = (float*)(s_raw + PART_OFF);

    int b = blockIdx.x;
    int t = threadIdx.x;

    sw[t] = g_W[(size_t)b * MDIM + t];

    // ---- Phase A: action tile -> fp16, XOR-swizzled 16B chunks
    {
        const float4* ga = (const float4*)(act + (size_t)b * nsk * 64);
        int ngroups = nsk * 8;
#pragma unroll 2
        for (int g = t; g < ngroups; g += 256) {
            float4 fa = ga[2 * g];
            float4 fb = ga[2 * g + 1];
            __half2 h0 = __floats2half2_rn(fa.x, fa.y);
            __half2 h1 = __floats2half2_rn(fa.z, fa.w);
            __half2 h2 = __floats2half2_rn(fb.x, fb.y);
            __half2 h3 = __floats2half2_rn(fb.z, fb.w);
            uint4 pk;
            pk.x = *(const unsigned*)&h0;
            pk.y = *(const unsigned*)&h1;
            pk.z = *(const unsigned*)&h2;
            pk.w = *(const unsigned*)&h3;
            unsigned off = ((unsigned)g << 4) ^ ((((unsigned)g >> 3) & 7u) << 4);
            *(uint4*)(sab + off) = pk;
        }
    }
    __syncthreads();

    // ---- Phase B: scores (f32x2, W pairs via LDS.128)
    {
        int half = (nsk + 1) >> 1;
        if (t < half) {
            int sk1 = t, sk2 = t + half;
            bool v2 = sk2 < nsk;
            unsigned swb1 = (unsigned)(sk1 * 128) | (((unsigned)sk1 & 7u) << 4);
            unsigned swb2 = (unsigned)(sk2 * 128) | (((unsigned)sk2 & 7u) << 4);
            ull a1[4] = {0, 0, 0, 0}, a2[4] = {0, 0, 0, 0};
#pragma unroll
            for (int i = 0; i < 8; i++) {
                uint4 av1 = *(const uint4*)(sab + (swb1 ^ ((unsigned)i << 4)));
                uint4 av2 = make_uint4(0, 0, 0, 0);
                if (v2) av2 = *(const uint4*)(sab + (swb2 ^ ((unsigned)i << 4)));
                ull d1[4] = {h2f2(av1.x), h2f2(av1.y), h2f2(av1.z), h2f2(av1.w)};
                ull d2[4] = {h2f2(av2.x), h2f2(av2.y), h2f2(av2.z), h2f2(av2.w)};
#pragma unroll
                for (int h = 0; h < 4; h++) {
                    ulonglong2 wA = *(const ulonglong2*)(sw + h * 64 + i * 8);
                    ulonglong2 wB = *(const ulonglong2*)(sw + h * 64 + i * 8 + 4);
                    a1[h] = fma2(d1[0], wA.x, a1[h]);
                    a1[h] = fma2(d1[1], wA.y, a1[h]);
                    a1[h] = fma2(d1[2], wB.x, a1[h]);
                    a1[h] = fma2(d1[3], wB.y, a1[h]);
                    a2[h] = fma2(d2[0], wA.x, a2[h]);
                    a2[h] = fma2(d2[1], wA.y, a2[h]);
                    a2[h] = fma2(d2[2], wB.x, a2[h]);
                    a2[h] = fma2(d2[3], wB.y, a2[h]);
                }
            }
            float s1[4], s2[4];
#pragma unroll
            for (int h = 0; h < 4; h++) {
                float2 f1 = unpack2(a1[h]); s1[h] = f1.x + f1.y;
                float2 f2 = unpack2(a2[h]); s2[h] = f2.x + f2.y;
            }
            scu[0 * SKPAD + sk1] = pack2(s1[0], s1[1]);
            scu[1 * SKPAD + sk1] = pack2(s1[2], s1[3]);
            if (v2) {
                scu[0 * SKPAD + sk2] = pack2(s2[0], s2[1]);
                scu[1 * SKPAD + sk2] = pack2(s2[2], s2[3]);
            }
        }
    }
    __syncthreads();

    // ---- Phase C: softmax, warp hp per head-pair, scores cached in regs
    {
        int wid = t >> 5, lane = t & 31;
        if (wid < 2) {
            int base = wid * SKPAD;
            ull vals[7];
            float mx = -1e30f, my = -1e30f;
#pragma unroll
            for (int r = 0; r < 7; r++) {
                int sk = lane + r * 32;
                vals[r] = (sk < nsk) ? scu[base + sk] : pack2(-1e30f, -1e30f);
                float2 f = unpack2(vals[r]);
                mx = fmaxf(mx, f.x);
                my = fmaxf(my, f.y);
            }
#pragma unroll
            for (int o = 16; o; o >>= 1) {
                mx = fmaxf(mx, __shfl_xor_sync(0xffffffffu, mx, o));
                my = fmaxf(my, __shfl_xor_sync(0xffffffffu, my, o));
            }
            float sx = 0.f, sy = 0.f;
#pragma unroll
            for (int r = 0; r < 7; r++) {
                int sk = lane + r * 32;
                if (sk < nsk) {
                    float2 f = unpack2(vals[r]);
                    float px = __expf(f.x - mx);
                    float py = __expf(f.y - my);
                    sx += px; sy += py;
                    scu[base + sk] = pack2(px, py);
                }
            }
#pragma unroll
            for (int o = 16; o; o >>= 1) {
                sx += __shfl_xor_sync(0xffffffffu, sx, o);
                sy += __shfl_xor_sync(0xffffffffu, sy, o);
            }
            if (lane == 0) {
                sinv[wid * 2]     = 1.f / sx;
                sinv[wid * 2 + 1] = 1.f / sy;
            }
        }
    }
    __syncthreads();

    // ---- Phase D: ctx partials. 128 threads = 16 sk-groups x 8 dim-octets,
    //      each accumulates ALL 4 heads (tile read once, not per head-pair).
    if (t < 128) {
        int sg = t >> 3, c8 = t & 7;
        ull acc[16];
#pragma unroll
        for (int v = 0; v < 16; v++) acc[v] = 0ull;

        int sk0 = sg * 13;
        int sk1e = sk0 + 13; if (sk1e > nsk) sk1e = nsk;
        for (int sk = sk0; sk < sk1e; sk++) {
            unsigned off = (unsigned)(sk * 128) |
                           ((((unsigned)sk & 7u) ^ (unsigned)c8) << 4);
            uint4 av = *(const uint4*)(sab + off);
            ull d0 = h2f2(av.x), d1 = h2f2(av.y), d2 = h2f2(av.z), d3 = h2f2(av.w);
            float2 p01 = unpack2(scu[sk]);
            float2 p23 = unpack2(scu[SKPAD + sk]);
            ull ph0 = pack2(p01.x, p01.x), ph1 = pack2(p01.y, p01.y);
            ull ph2 = pack2(p23.x, p23.x), ph3 = pack2(p23.y, p23.y);
            acc[0]  = fma2(ph0, d0, acc[0]);  acc[1]  = fma2(ph0, d1, acc[1]);
            acc[2]  = fma2(ph0, d2, acc[2]);  acc[3]  = fma2(ph0, d3, acc[3]);
            acc[4]  = fma2(ph1, d0, acc[4]);  acc[5]  = fma2(ph1, d1, acc[5]);
            acc[6]  = fma2(ph1, d2, acc[6]);  acc[7]  = fma2(ph1, d3, acc[7]);
            acc[8]  = fma2(ph2, d0, acc[8]);  acc[9]  = fma2(ph2, d1, acc[9]);
            acc[10] = fma2(ph2, d2, acc[10]); acc[11] = fma2(ph2, d3, acc[11]);
            acc[12] = fma2(ph3, d0, acc[12]); acc[13] = fma2(ph3, d1, acc[13]);
            acc[14] = fma2(ph3, d2, acc[14]); acc[15] = fma2(ph3, d3, acc[15]);
        }
        // reduce over 4 sk-groups within warp (lane bits 3,4)
#pragma unroll
        for (int v = 0; v < 16; v++) {
            acc[v] = add2(acc[v], __shfl_xor_sync(0xffffffffu, acc[v], 8));
            acc[v] = add2(acc[v], __shfl_xor_sync(0xffffffffu, acc[v], 16));
        }
        if ((t & 24) == 0) {          // sg%4 == 0 lanes hold warp partial
            int w = t >> 5;
            ull* pw = (ull*)partf + w * 128 + c8 * 4;
#pragma unroll
            for (int h = 0; h < 4; h++)
#pragma unroll
                for (int p = 0; p < 4; p++)
                    pw[h * 32 + p] = acc[h * 4 + p];
        }
    }
    __syncthreads();

    // ---- Phase E: combine 4 warp-partials -> normalized ctx into sw
    {
        float r = partf[t] + partf[256 + t] + partf[512 + t] + partf[768 + t];
        sw[t] = r * sinv[t >> 6];
    }
    __syncthreads();

    // ---- Phase F: out[c] = sum_a ctx[h(c)*64+a] * V[a][c]  (f32x2)
    if (t < 64) {
        int c = t, h = t >> 4;
        const ull* cx = (const ull*)(sw + h * 64);
        ull acc2 = 0ull;
#pragma unroll 8
        for (int a = 0; a < 32; a++) {
            float v0 = __ldg(V + (size_t)(2 * a) * 64 + c);
            float v1 = __ldg(V + (size_t)(2 * a + 1) * 64 + c);
            acc2 = fma2(cx[a], pack2(v0, v1), acc2);
        }
        float2 f = unpack2(acc2);
        out[(size_t)b * 64 + c] = f.x + f.y;
    }
}

// ---------------------------------------------------------------------------
extern "C" void kernel_launch(void* const* d_in, const int* in_sizes, int n_in,
                              void* d_out, int out_size) {
    const float* query = (const float*)d_in[0];   // [B,1,64]
    const float* act   = (const float*)d_in[1];   // [B,SK,64]
    const float* Q     = (const float*)d_in[2];   // [64,64]
    const float* K     = (const float*)d_in[3];   // [64,64]
    const float* V     = (const float*)d_in[4];   // [64,64]
    float* out = (float*)d_out;

    int B   = in_sizes[0] / COLD;
    int nsk = in_sizes[1] / (B * AISD);
    if (nsk > SKPAD) nsk = SKPAD;

    cudaFuncSetAttribute(k2_fused, cudaFuncAttributeMaxDynamicSharedMemorySize, SMEM_BYTES);

    k1_w<<<(B + 15) / 16, 256>>>(query, Q, K, B);
    k2_fused<<<B, 256, SMEM_BYTES>>>(act, V, out, nsk);
}

// round 5
// speedup vs baseline: 1.1110x; 1.1110x over previous
#include <cuda_runtime.h>
#include <cuda_fp16.h>

#define NHEAD 4
#define COLD  64
#define AISD  64
#define MDIM  256
#define SKPAD 208
#define BMAX  8192

__device__ float g_W[(size_t)BMAX * MDIM];   // 8 MB scratch

typedef unsigned long long ull;

// ---- packed fp32x2 helpers ----
__device__ __forceinline__ ull fma2(ull a, ull b, ull c) {
    ull d;
    asm("fma.rn.f32x2 %0, %1, %2, %3;" : "=l"(d) : "l"(a), "l"(b), "l"(c));
    return d;
}
__device__ __forceinline__ ull add2(ull a, ull b) {
    ull d;
    asm("add.rn.f32x2 %0, %1, %2;" : "=l"(d) : "l"(a), "l"(b));
    return d;
}
__device__ __forceinline__ ull pack2(float x, float y) {
    ull r;
    asm("mov.b64 %0, {%1, %2};" : "=l"(r) : "f"(x), "f"(y));
    return r;
}
__device__ __forceinline__ float2 unpack2(ull a) {
    float2 f;
    asm("mov.b64 {%0, %1}, %2;" : "=f"(f.x), "=f"(f.y) : "l"(a));
    return f;
}
__device__ __forceinline__ ull h2f2(unsigned h) {
    ull r;
    asm("{\n\t.reg .b16 lo, hi;\n\t.reg .f32 flo, fhi;\n\t"
        "mov.b32 {lo, hi}, %1;\n\t"
        "cvt.f32.f16 flo, lo;\n\tcvt.f32.f16 fhi, hi;\n\t"
        "mov.b64 %0, {flo, fhi};\n\t}" : "=l"(r) : "r"(h));
    return r;
}

// ---------------------------------------------------------------------------
// K1: W[b][h*64+a] = (1/8) sum_j (q[b]@Q)[h*16+j] * K[a][h*16+j]
// 16 batches/CTA, K staged in padded smem.
// ---------------------------------------------------------------------------
__global__ __launch_bounds__(256) void k1_w(const float* __restrict__ query,
                                            const float* __restrict__ Q,
                                            const float* __restrict__ Kw, int B) {
    __shared__ float sK[64 * 68];
    __shared__ float qT[64 * 20];
    __shared__ float qp[16 * 64];
    int b0 = blockIdx.x * 16, t = threadIdx.x;

#pragma unroll
    for (int p = 0; p < 4; p++) {
        int bb = p * 4 + (t >> 6), i = t & 63;
        float v = (b0 + bb < B) ? query[(size_t)(b0 + bb) * 64 + i] : 0.f;
        qT[i * 20 + bb] = v;
    }
    for (int idx = t; idx < 4096; idx += 256)
        sK[(idx >> 6) * 68 + (idx & 63)] = Kw[idx];
    __syncthreads();

    {
        int bq = t >> 6, c = t & 63;
        float a0 = 0.f, a1 = 0.f, a2 = 0.f, a3 = 0.f;
#pragma unroll 8
        for (int i = 0; i < 64; i++) {
            float qv = Q[i * 64 + c];
            float4 qb = *(const float4*)(qT + i * 20 + bq * 4);
            a0 += qb.x * qv; a1 += qb.y * qv; a2 += qb.z * qv; a3 += qb.w * qv;
        }
        qp[(bq * 4 + 0) * 64 + c] = a0;
        qp[(bq * 4 + 1) * 64 + c] = a1;
        qp[(bq * 4 + 2) * 64 + c] = a2;
        qp[(bq * 4 + 3) * 64 + c] = a3;
    }
    __syncthreads();

    {
        int h = t >> 6, a = t & 63;
        const float4* K4 = (const float4*)(sK + a * 68 + h * 16);
        float4 k0 = K4[0], k1 = K4[1], k2 = K4[2], k3 = K4[3];
#pragma unroll
        for (int bb = 0; bb < 16; bb++) {
            const float4* q4 = (const float4*)(qp + bb * 64 + h * 16);
            float4 qa = q4[0], qb = q4[1], qc = q4[2], qd = q4[3];
            float wv = qa.x * k0.x + qa.y * k0.y + qa.z * k0.z + qa.w * k0.w
                     + qb.x * k1.x + qb.y * k1.y + qb.z * k1.z + qb.w * k1.w
                     + qc.x * k2.x + qc.y * k2.y + qc.z * k2.z + qc.w * k2.w
                     + qd.x * k3.x + qd.y * k3.y + qd.z * k3.z + qd.w * k3.w;
            if (b0 + bb < B)
                g_W[(size_t)(b0 + bb) * MDIM + t] = 0.125f * wv;
        }
    }
}

// ---------------------------------------------------------------------------
// K2: fused attention + output, 128-thread CTA per batch, 7 CTAs/SM.
// smem: tile (reused for partials after Phase D) + W/ctx + scores + sinv.
// ---------------------------------------------------------------------------
#define SA_BYTES   (SKPAD * 128)             // 26624 fp16 swizzled tile (aliased by partials later)
#define SW_OFF     SA_BYTES                  // 1024: W row, later ctx
#define SC_OFF     (SW_OFF + 1024)           // 3328: packed scores ull[2][SKPAD]
#define SINV_OFF   (SC_OFF + 3328)           // 32
#define SMEM_BYTES (SINV_OFF + 32)           // 31008 total

extern __shared__ char s_raw[];

__global__ __launch_bounds__(128, 7) void k2_fused(const float* __restrict__ act,
                                                   const float* __restrict__ V,
                                                   float* __restrict__ out, int nsk) {
    char*  sab   = s_raw;
    float* sw    = (float*)(s_raw + SW_OFF);
    ull*   scu   = (ull*)(s_raw + SC_OFF);
    float* sinv  = (float*)(s_raw + SINV_OFF);
    float* partf = (float*)s_raw;            // aliases tile after Phase D

    int b = blockIdx.x;
    int t = threadIdx.x;

    sw[t]       = g_W[(size_t)b * MDIM + t];
    sw[t + 128] = g_W[(size_t)b * MDIM + t + 128];

    // ---- Phase A: action tile -> fp16, XOR-swizzled 16B chunks
    {
        const float4* ga = (const float4*)(act + (size_t)b * nsk * 64);
        int ngroups = nsk * 8;
#pragma unroll 2
        for (int g = t; g < ngroups; g += 128) {
            float4 fa = ga[2 * g];
            float4 fb = ga[2 * g + 1];
            __half2 h0 = __floats2half2_rn(fa.x, fa.y);
            __half2 h1 = __floats2half2_rn(fa.z, fa.w);
            __half2 h2 = __floats2half2_rn(fb.x, fb.y);
            __half2 h3 = __floats2half2_rn(fb.z, fb.w);
            uint4 pk;
            pk.x = *(const unsigned*)&h0;
            pk.y = *(const unsigned*)&h1;
            pk.z = *(const unsigned*)&h2;
            pk.w = *(const unsigned*)&h3;
            unsigned off = ((unsigned)g << 4) ^ ((((unsigned)g >> 3) & 7u) << 4);
            *(uint4*)(sab + off) = pk;
        }
    }
    __syncthreads();

    // ---- Phase B: scores (f32x2). Thread t handles sk = t and sk = t + 128.
    {
        int sk1 = t, sk2 = t + 128;
        bool v1 = sk1 < nsk, v2 = sk2 < nsk;
        if (v1) {
            unsigned swb1 = (unsigned)(sk1 * 128) | (((unsigned)sk1 & 7u) << 4);
            unsigned swb2 = (unsigned)(sk2 * 128) | (((unsigned)sk2 & 7u) << 4);
            ull a1[4] = {0, 0, 0, 0}, a2[4] = {0, 0, 0, 0};
#pragma unroll
            for (int i = 0; i < 8; i++) {
                uint4 av1 = *(const uint4*)(sab + (swb1 ^ ((unsigned)i << 4)));
                uint4 av2 = make_uint4(0, 0, 0, 0);
                if (v2) av2 = *(const uint4*)(sab + (swb2 ^ ((unsigned)i << 4)));
                ull d1[4] = {h2f2(av1.x), h2f2(av1.y), h2f2(av1.z), h2f2(av1.w)};
                ull d2[4] = {h2f2(av2.x), h2f2(av2.y), h2f2(av2.z), h2f2(av2.w)};
#pragma unroll
                for (int h = 0; h < 4; h++) {
                    ulonglong2 wA = *(const ulonglong2*)(sw + h * 64 + i * 8);
                    ulonglong2 wB = *(const ulonglong2*)(sw + h * 64 + i * 8 + 4);
                    a1[h] = fma2(d1[0], wA.x, a1[h]);
                    a1[h] = fma2(d1[1], wA.y, a1[h]);
                    a1[h] = fma2(d1[2], wB.x, a1[h]);
                    a1[h] = fma2(d1[3], wB.y, a1[h]);
                    a2[h] = fma2(d2[0], wA.x, a2[h]);
                    a2[h] = fma2(d2[1], wA.y, a2[h]);
                    a2[h] = fma2(d2[2], wB.x, a2[h]);
                    a2[h] = fma2(d2[3], wB.y, a2[h]);
                }
            }
            float s1[4], s2[4];
#pragma unroll
            for (int h = 0; h < 4; h++) {
                float2 f1 = unpack2(a1[h]); s1[h] = f1.x + f1.y;
                float2 f2 = unpack2(a2[h]); s2[h] = f2.x + f2.y;
            }
            scu[0 * SKPAD + sk1] = pack2(s1[0], s1[1]);
            scu[1 * SKPAD + sk1] = pack2(s1[2], s1[3]);
            if (v2) {
                scu[0 * SKPAD + sk2] = pack2(s2[0], s2[1]);
                scu[1 * SKPAD + sk2] = pack2(s2[2], s2[3]);
            }
        }
    }
    __syncthreads();

    // ---- Phase C: softmax, warps 0/1 = head pairs, scores cached in regs
    {
        int wid = t >> 5, lane = t & 31;
        if (wid < 2) {
            int base = wid * SKPAD;
            ull vals[7];
            float mx = -1e30f, my = -1e30f;
#pragma unroll
            for (int r = 0; r < 7; r++) {
                int sk = lane + r * 32;
                vals[r] = (sk < nsk) ? scu[base + sk] : pack2(-1e30f, -1e30f);
                float2 f = unpack2(vals[r]);
                mx = fmaxf(mx, f.x);
                my = fmaxf(my, f.y);
            }
#pragma unroll
            for (int o = 16; o; o >>= 1) {
                mx = fmaxf(mx, __shfl_xor_sync(0xffffffffu, mx, o));
                my = fmaxf(my, __shfl_xor_sync(0xffffffffu, my, o));
            }
            float sx = 0.f, sy = 0.f;
#pragma unroll
            for (int r = 0; r < 7; r++) {
                int sk = lane + r * 32;
                if (sk < nsk) {
                    float2 f = unpack2(vals[r]);
                    float px = __expf(f.x - mx);
                    float py = __expf(f.y - my);
                    sx += px; sy += py;
                    scu[base + sk] = pack2(px, py);
                }
            }
#pragma unroll
            for (int o = 16; o; o >>= 1) {
                sx += __shfl_xor_sync(0xffffffffu, sx, o);
                sy += __shfl_xor_sync(0xffffffffu, sy, o);
            }
            if (lane == 0) {
                sinv[wid * 2]     = 1.f / sx;
                sinv[wid * 2 + 1] = 1.f / sy;
            }
        }
    }
    __syncthreads();

    // ---- Phase D: ctx partials. 128 threads = 16 sk-groups x 8 dim-octets,
    //      each accumulates all 4 heads. Tile read once.
    ull acc[16];
    {
        int sg = t >> 3, c8 = t & 7;
#pragma unroll
        for (int v = 0; v < 16; v++) acc[v] = 0ull;

        int sk0 = sg * 13;
        int sk1e = sk0 + 13; if (sk1e > nsk) sk1e = nsk;
        for (int sk = sk0; sk < sk1e; sk++) {
            unsigned off = (unsigned)(sk * 128) |
                           ((((unsigned)sk & 7u) ^ (unsigned)c8) << 4);
            uint4 av = *(const uint4*)(sab + off);
            ull d0 = h2f2(av.x), d1 = h2f2(av.y), d2 = h2f2(av.z), d3 = h2f2(av.w);
            float2 p01 = unpack2(scu[sk]);
            float2 p23 = unpack2(scu[SKPAD + sk]);
            ull ph0 = pack2(p01.x, p01.x), ph1 = pack2(p01.y, p01.y);
            ull ph2 = pack2(p23.x, p23.x), ph3 = pack2(p23.y, p23.y);
            acc[0]  = fma2(ph0, d0, acc[0]);  acc[1]  = fma2(ph0, d1, acc[1]);
            acc[2]  = fma2(ph0, d2, acc[2]);  acc[3]  = fma2(ph0, d3, acc[3]);
            acc[4]  = fma2(ph1, d0, acc[4]);  acc[5]  = fma2(ph1, d1, acc[5]);
            acc[6]  = fma2(ph1, d2, acc[6]);  acc[7]  = fma2(ph1, d3, acc[7]);
            acc[8]  = fma2(ph2, d0, acc[8]);  acc[9]  = fma2(ph2, d1, acc[9]);
            acc[10] = fma2(ph2, d2, acc[10]); acc[11] = fma2(ph2, d3, acc[11]);
            acc[12] = fma2(ph3, d0, acc[12]); acc[13] = fma2(ph3, d1, acc[13]);
            acc[14] = fma2(ph3, d2, acc[14]); acc[15] = fma2(ph3, d3, acc[15]);
        }
#pragma unroll
        for (int v = 0; v < 16; v++) {
            acc[v] = add2(acc[v], __shfl_xor_sync(0xffffffffu, acc[v], 8));
            acc[v] = add2(acc[v], __shfl_xor_sync(0xffffffffu, acc[v], 16));
        }
    }
    __syncthreads();   // tile reads done everywhere; safe to alias with partials

    {
        int c8 = t & 7;
        if ((t & 24) == 0) {                  // lanes with sg%4 == 0
            int w = t >> 5;
            ull* pw = (ull*)partf + w * 128 + c8 * 4;
#pragma unroll
            for (int h = 0; h < 4; h++)
#pragma unroll
                for (int p = 0; p < 4; p++)
                    pw[h * 32 + p] = acc[h * 4 + p];
        }
    }
    __syncthreads();

    // ---- Phase E: combine 4 warp-partials -> normalized ctx into sw
    {
        float r0 = partf[t]       + partf[256 + t]       + partf[512 + t]       + partf[768 + t];
        float r1 = partf[t + 128] + partf[256 + t + 128] + partf[512 + t + 128] + partf[768 + t + 128];
        sw[t]       = r0 * sinv[t >> 6];
        sw[t + 128] = r1 * sinv[(t + 128) >> 6];
    }
    __syncthreads();

    // ---- Phase F: out[c] = sum_a ctx[h(c)*64+a] * V[a][c]  (f32x2)
    if (t < 64) {
        int c = t, h = t >> 4;
        const ull* cx = (const ull*)(sw + h * 64);
        ull acc2 = 0ull;
#pragma unroll 8
        for (int a = 0; a < 32; a++) {
            float v0 = __ldg(V + (size_t)(2 * a) * 64 + c);
            float v1 = __ldg(V + (size_t)(2 * a + 1) * 64 + c);
            acc2 = fma2(cx[a], pack2(v0, v1), acc2);
        }
        float2 f = unpack2(acc2);
        out[(size_t)b * 64 + c] = f.x + f.y;
    }
}

// ---------------------------------------------------------------------------
extern "C" void kernel_launch(void* const* d_in, const int* in_sizes, int n_in,
                              void* d_out, int out_size) {
    const float* query = (const float*)d_in[0];   // [B,1,64]
    const float* act   = (const float*)d_in[1];   // [B,SK,64]
    const float* Q     = (const float*)d_in[2];   // [64,64]
    const float* K     = (const float*)d_in[3];   // [64,64]
    const float* V     = (const float*)d_in[4];   // [64,64]
    float* out = (float*)d_out;

    int B   = in_sizes[0] / COLD;
    int nsk = in_sizes[1] / (B * AISD);
    if (nsk > SKPAD) nsk = SKPAD;

    cudaFuncSetAttribute(k2_fused, cudaFuncAttributeMaxDynamicSharedMemorySize, SMEM_BYTES);

    k1_w<<<(B + 15) / 16, 256>>>(query, Q, K, B);
    k2_fused<<<B, 128, SMEM_BYTES>>>(act, V, out, nsk);
}